// round 13
// baseline (speedup 1.0000x reference)
#include <cuda_runtime.h>
#include <cuda_bf16.h>
#include <math.h>

#define BB   64
#define NN   197
#define CC   768
#define HH   12
#define DD   64
#define DICN 1000
#define TOK  (BB*NN)           // 12608 = 64*197
#define QKC  1536              // q||k columns in g_qkh/g_qkl
#define WROWS 1664             // 1536 qk rows + 48 M rows + 80 pad = 13*128

typedef unsigned long long ull;
typedef unsigned int u32;

// ---- mma.sync / ldmatrix / cp.async helpers (baseline PTX, sm_80+) ----
__device__ __forceinline__ u32 smem_u32(const void* p) {
    u32 a; asm("{ .reg .u64 t; cvta.to.shared.u64 t, %1; cvt.u32.u64 %0, t; }" : "=r"(a) : "l"(p));
    return a;
}
__device__ __forceinline__ void ldsm4(u32& r0, u32& r1, u32& r2, u32& r3, u32 addr) {
    asm volatile("ldmatrix.sync.aligned.m8n8.x4.shared.b16 {%0,%1,%2,%3}, [%4];"
                 : "=r"(r0), "=r"(r1), "=r"(r2), "=r"(r3) : "r"(addr));
}
__device__ __forceinline__ void mma16816(float* d, const u32* a, u32 b0, u32 b1) {
    asm volatile("mma.sync.aligned.m16n8k16.row.col.f32.bf16.bf16.f32 "
                 "{%0,%1,%2,%3},{%4,%5,%6,%7},{%8,%9},{%0,%1,%2,%3};"
                 : "+f"(d[0]), "+f"(d[1]), "+f"(d[2]), "+f"(d[3])
                 : "r"(a[0]), "r"(a[1]), "r"(a[2]), "r"(a[3]), "r"(b0), "r"(b1));
}
__device__ __forceinline__ void cp16(u32 dst, const void* src) {
    asm volatile("cp.async.cg.shared.global [%0], [%1], 16;" :: "r"(dst), "l"(src) : "memory");
}
__device__ __forceinline__ void cp_commit() {
    asm volatile("cp.async.commit_group;" ::: "memory");
}

// split a float4 into bf16-hi (8B) and bf16-lo (8B)
__device__ __forceinline__ void split4(float4 v, uint2& hi, uint2& lo) {
    __nv_bfloat16 h0 = __float2bfloat16(v.x);
    __nv_bfloat16 h1 = __float2bfloat16(v.y);
    __nv_bfloat16 h2 = __float2bfloat16(v.z);
    __nv_bfloat16 h3 = __float2bfloat16(v.w);
    __nv_bfloat162 ph0(h0, h1), ph1(h2, h3);
    hi.x = *(u32*)&ph0; hi.y = *(u32*)&ph1;
    __nv_bfloat162 pl0(__float2bfloat16(v.x - __bfloat162float(h0)),
                       __float2bfloat16(v.y - __bfloat162float(h1)));
    __nv_bfloat162 pl1(__float2bfloat16(v.z - __bfloat162float(h2)),
                       __float2bfloat16(v.w - __bfloat162float(h3)));
    lo.x = *(u32*)&pl0; lo.y = *(u32*)&pl1;
}
// split a pair of floats into packed bf16x2 hi and lo
__device__ __forceinline__ void split2(float x, float y, u32& hi, u32& lo) {
    __nv_bfloat16 h0 = __float2bfloat16(x), h1 = __float2bfloat16(y);
    __nv_bfloat162 ph(h0, h1);
    hi = *(u32*)&ph;
    __nv_bfloat162 pl(__float2bfloat16(x - __bfloat162float(h0)),
                      __float2bfloat16(y - __bfloat162float(h1)));
    lo = *(u32*)&pl;
}

// ---------------- scratch ----------------
__device__ __nv_bfloat16 g_xh[TOK*CC];
__device__ __nv_bfloat16 g_xl[TOK*CC];
__device__ __nv_bfloat16 g_wh[WROWS*CC];
__device__ __nv_bfloat16 g_wl[WROWS*CC];
__device__ __nv_bfloat16 g_qkh[(size_t)TOK*QKC];  // bf16-hi of q(scaled)||k
__device__ __nv_bfloat16 g_qkl[(size_t)TOK*QKC];  // bf16-lo
__device__ float g_vz[BB*HH*NN*4];
__device__ float g_zpart[BB*HH*NN*4];
__device__ int   g_idx[TOK];
__device__ float g_P[CC*4];
__device__ float g_b2[CC];
__device__ float g_losspart[64];

// ---------------- fused bf16 hi/lo split conversion: x then qkv_w[0:1536] ----------------
#define XN4 (TOK*CC/4)
#define WN4 (1536*CC/4)
#define XBLK ((XN4 + 255) / 256)
#define WBLK ((WN4 + 255) / 256)

__global__ void conv_both(const float* __restrict__ x, const float* __restrict__ w,
                          __nv_bfloat16* __restrict__ xh, __nv_bfloat16* __restrict__ xl,
                          __nv_bfloat16* __restrict__ wh, __nv_bfloat16* __restrict__ wl)
{
    int blk = blockIdx.x;
    const float* src; __nv_bfloat16 *hi, *lo; int i, n4;
    if (blk < XBLK) {
        i = blk * 256 + threadIdx.x; n4 = XN4;
        src = x; hi = xh; lo = xl;
    } else {
        i = (blk - XBLK) * 256 + threadIdx.x; n4 = WN4;
        src = w; hi = wh; lo = wl;
    }
    if (i >= n4) return;
    float4 v = *(const float4*)(src + (size_t)i*4);
    uint2 h, l;
    split4(v, h, l);
    *(uint2*)(hi + (size_t)i*4) = h;
    *(uint2*)(lo + (size_t)i*4) = l;
}

// ---------------- prep: M row r=h*4+j of W (rows 1536..1583), bf16 hi/lo direct ----------------
__global__ void prep_m(const float* __restrict__ qkv_w, const float* __restrict__ vq_in_w)
{
    int h = blockIdx.x >> 2, j = blockIdx.x & 3;
    int r = 1536 + h*4 + j;
    for (int c = threadIdx.x; c < CC; c += blockDim.x) {
        float s = 0.f;
        #pragma unroll 8
        for (int d = 0; d < DD; d++)
            s = fmaf(qkv_w[(size_t)(2*CC + h*DD + d)*CC + c], vq_in_w[j*CC + h*DD + d], s);
        __nv_bfloat16 hb = __float2bfloat16(s);
        g_wh[(size_t)r*CC + c] = hb;
        g_wl[(size_t)r*CC + c] = __float2bfloat16(s - __bfloat162float(hb));
    }
}

__global__ void prep_p(const float* __restrict__ proj_w, const float* __restrict__ proj_b,
                       const float* __restrict__ vq_out_w, const float* __restrict__ vq_out_b)
{
    int wid = threadIdx.x >> 5, lane = threadIdx.x & 31;
    int o = blockIdx.x * 8 + wid;
    if (o >= CC) return;
    float p0=0.f,p1=0.f,p2=0.f,p3=0.f,bb=0.f;
    for (int c = lane; c < CC; c += 32) {
        float w = proj_w[(size_t)o*CC + c];
        float4 vo = *(const float4*)(vq_out_w + c*4);
        p0 = fmaf(w, vo.x, p0); p1 = fmaf(w, vo.y, p1);
        p2 = fmaf(w, vo.z, p2); p3 = fmaf(w, vo.w, p3);
        bb = fmaf(w, vq_out_b[c], bb);
    }
    #pragma unroll
    for (int off = 16; off; off >>= 1) {
        p0 += __shfl_xor_sync(0xffffffffu, p0, off);
        p1 += __shfl_xor_sync(0xffffffffu, p1, off);
        p2 += __shfl_xor_sync(0xffffffffu, p2, off);
        p3 += __shfl_xor_sync(0xffffffffu, p3, off);
        bb += __shfl_xor_sync(0xffffffffu, bb, off);
    }
    if (lane == 0) {
        *(float4*)(g_P + o*4) = make_float4(p0, p1, p2, p3);
        g_b2[o] = bb + proj_b[o];
    }
}

// ---------------- qk+vz GEMM on HMMA: [12608,768] x W[1664,768]^T ----------------
// CTA: 256 threads, 64(M) x 128(N) tile, warp grid 2(m) x 4(n), warp tile 32x32.
// Stage 48KB (Ah 8K, Al 8K, Bh 16K, Bl 16K), 2 stages = 96KB -> 2 CTAs/SM, 16 warps/SM.
// n-tiles 0..11: q||k -> bf16 hi/lo store. n-tile 12: vz (48 cols) -> fp32 scatter.
#define STAGE 49152

__global__ void __launch_bounds__(256, 2) qk_mma()
{
    extern __shared__ __align__(128) char smem[];
    u32 sbase = smem_u32(smem);
    int tid = threadIdx.x;
    int wid = tid >> 5, lane = tid & 31;
    int wm = wid >> 2;                  // 0..1 (m half)
    int wn = wid & 3;                   // 0..3 (n quarter)
    int m0 = blockIdx.y * 64;           // 197 m-tiles, exact
    int c0 = blockIdx.x * 128;

    int q = lane >> 3, lr = lane & 7;
    u32 arow[2], asw[2];
    #pragma unroll
    for (int mf = 0; mf < 2; mf++) {
        int r = wm*32 + mf*16 + ((q & 1) << 3) + lr;  // 0..63
        arow[mf] = (u32)(r * 128);
        asw[mf]  = (u32)((r & 7) << 4);
    }
    u32 akb = (u32)((q >> 1) << 4);
    u32 brow[2], bsw[2];
    #pragma unroll
    for (int g = 0; g < 2; g++) {
        int nr = wn*32 + g*16 + ((q >> 1) << 3) + lr; // 0..127
        brow[g] = (u32)(nr * 128);
        bsw[g]  = (u32)((nr & 7) << 4);
    }
    u32 bkb = (u32)((q & 1) << 4);

    float acc[2][4][4];
    #pragma unroll
    for (int a = 0; a < 2; a++)
        #pragma unroll
        for (int b = 0; b < 4; b++)
            #pragma unroll
            for (int c = 0; c < 4; c++) acc[a][b][c] = 0.f;

    auto fill = [&](int buf, int t) {
        int k0 = t * 64;
        u32 db = sbase + buf*STAGE;
        // A: 64 rows x 8 16B-chunks, hi+lo
        #pragma unroll
        for (int i = 0; i < 2; i++) {
            int u = i*256 + tid;
            int row = u >> 3, ku = u & 7;
            u32 soff = (u32)(row*128 + ((ku*16) ^ ((row & 7) << 4)));
            size_t aoff = (size_t)(m0 + row)*CC + k0 + ku*8;
            cp16(db + soff,        g_xh + aoff);
            cp16(db + 8192 + soff, g_xl + aoff);
        }
        // B: 128 rows x 8 16B-chunks, hi+lo
        #pragma unroll
        for (int i = 0; i < 4; i++) {
            int u = i*256 + tid;
            int row = u >> 3, ku = u & 7;
            u32 soff = (u32)(row*128 + ((ku*16) ^ ((row & 7) << 4)));
            size_t boff = (size_t)(c0 + row)*CC + k0 + ku*8;
            cp16(db + 16384 + soff, g_wh + boff);
            cp16(db + 32768 + soff, g_wl + boff);
        }
        cp_commit();
    };

    fill(0, 0);
    for (int t = 0; t < 12; t++) {
        int buf = t & 1;
        if (t + 1 < 12) {
            fill(buf ^ 1, t + 1);
            asm volatile("cp.async.wait_group 1;" ::: "memory");
        } else {
            asm volatile("cp.async.wait_group 0;" ::: "memory");
        }
        __syncthreads();

        u32 Ab  = sbase + buf*STAGE;
        u32 Alb = Ab + 8192;
        u32 Bb  = Ab + 16384;
        u32 Blb = Ab + 32768;
        #pragma unroll
        for (int ks = 0; ks < 4; ks++) {
            u32 kb = (u32)(ks * 32);
            u32 Ah[2][4], Al[2][4], Bh[2][4], Bl[2][4];
            #pragma unroll
            for (int mf = 0; mf < 2; mf++) {
                u32 colA = (kb + akb) ^ asw[mf];
                ldsm4(Ah[mf][0], Ah[mf][1], Ah[mf][2], Ah[mf][3], Ab  + arow[mf] + colA);
                ldsm4(Al[mf][0], Al[mf][1], Al[mf][2], Al[mf][3], Alb + arow[mf] + colA);
            }
            #pragma unroll
            for (int g = 0; g < 2; g++) {
                u32 colB = (kb + bkb) ^ bsw[g];
                ldsm4(Bh[g][0], Bh[g][1], Bh[g][2], Bh[g][3], Bb  + brow[g] + colB);
                ldsm4(Bl[g][0], Bl[g][1], Bl[g][2], Bl[g][3], Blb + brow[g] + colB);
            }
            #pragma unroll
            for (int mf = 0; mf < 2; mf++) {
                #pragma unroll
                for (int g = 0; g < 2; g++) {
                    mma16816(acc[mf][2*g],   Ah[mf], Bh[g][0], Bh[g][1]);
                    mma16816(acc[mf][2*g+1], Ah[mf], Bh[g][2], Bh[g][3]);
                    mma16816(acc[mf][2*g],   Ah[mf], Bl[g][0], Bl[g][1]);
                    mma16816(acc[mf][2*g+1], Ah[mf], Bl[g][2], Bl[g][3]);
                    mma16816(acc[mf][2*g],   Al[mf], Bh[g][0], Bh[g][1]);
                    mma16816(acc[mf][2*g+1], Al[mf], Bh[g][2], Bh[g][3]);
                }
            }
        }
        __syncthreads();
    }

    int rb = m0 + wm*32 + (lane >> 2);
    int nb = c0 + wn*32 + (lane & 3)*2;
    if (c0 < 1536) {
        float scale = (c0 < 768) ? 0.125f : 1.0f;
        #pragma unroll
        for (int mf = 0; mf < 2; mf++) {
            #pragma unroll
            for (int nf = 0; nf < 4; nf++) {
                int r = rb + mf*16;
                int n = nb + nf*8;
                u32 hi, lo;
                split2(acc[mf][nf][0]*scale, acc[mf][nf][1]*scale, hi, lo);
                *(u32*)(g_qkh + (size_t)r*QKC + n) = hi;
                *(u32*)(g_qkl + (size_t)r*QKC + n) = lo;
                split2(acc[mf][nf][2]*scale, acc[mf][nf][3]*scale, hi, lo);
                *(u32*)(g_qkh + (size_t)(r+8)*QKC + n) = hi;
                *(u32*)(g_qkl + (size_t)(r+8)*QKC + n) = lo;
            }
        }
    } else {
        // vz tile: cols 1536..1583 valid -> scatter fp32 into g_vz[b,h,n,4]
        #pragma unroll
        for (int mf = 0; mf < 2; mf++) {
            #pragma unroll
            for (int nf = 0; nf < 4; nf++) {
                int col = nb + nf*8 - 1536;
                if (col >= 48) continue;
                #pragma unroll
                for (int rr = 0; rr < 2; rr++) {
                    int r = rb + mf*16 + rr*8;
                    int bb2 = r / NN, nn = r - bb2*NN;
                    float v0 = acc[mf][nf][rr*2], v1 = acc[mf][nf][rr*2 + 1];
                    g_vz[((size_t)(bb2*HH + (col >> 2))*NN + nn)*4 + (col & 3)] = v0;
                    if (col + 1 < 48)
                        g_vz[((size_t)(bb2*HH + ((col+1) >> 2))*NN + nn)*4 + ((col+1) & 3)] = v1;
                }
            }
        }
    }
}

// ---------------- fused attention on HMMA (loads prestored bf16 hi/lo) ----------------
#define ATTN_SMEM 109696

__global__ void __launch_bounds__(256) attn_kernel()
{
    extern __shared__ __align__(128) char sm[];
    u32 s_qh = smem_u32(sm);
    u32 s_kh = s_qh + 53248;
    float* vzs = (float*)(sm + 106496);

    int bh = blockIdx.x;
    int b = bh / HH, h = bh % HH;
    const __nv_bfloat16* qhp = g_qkh + (size_t)(b*NN)*QKC + h*64;
    const __nv_bfloat16* qlp = g_qkl + (size_t)(b*NN)*QKC + h*64;
    int tid = threadIdx.x;

    for (int u = tid; u < NN*8; u += 256) {
        int row = u >> 3, ch = u & 7;
        u32 off = (u32)(row*128 + ((ch*16) ^ ((row & 7) << 4)));
        size_t src = (size_t)row*QKC + ch*8;
        cp16(s_qh + off,         qhp + src);
        cp16(s_qh + 26624 + off, qlp + src);
        cp16(s_kh + off,         qhp + 768 + src);
        cp16(s_kh + 26624 + off, qlp + 768 + src);
    }
    cp_commit();
    for (int u = tid; u < 88; u += 256) {
        int row = 197 + (u >> 3), ch = u & 7;
        u32 off = (u32)(row*128 + ((ch*16) ^ ((row & 7) << 4)));
        uint4 z = make_uint4(0u,0u,0u,0u);
        *(uint4*)(sm + off)         = z;
        *(uint4*)(sm + 26624 + off) = z;
        *(uint4*)(sm + 53248 + off) = z;
        *(uint4*)(sm + 79872 + off) = z;
    }
    {
        size_t vb = (size_t)bh*NN*4;
        for (int i = tid; i < 200*4; i += 256)
            vzs[i] = (i < NN*4) ? g_vz[vb + i] : 0.f;
    }
    asm volatile("cp.async.wait_group 0;" ::: "memory");
    __syncthreads();

    int lane = tid & 31, wid = tid >> 5;
    int qq = lane >> 3, lr = lane & 7;
    u32 lsw = (u32)(lr << 4);
    u32 a_row = (u32)((((qq & 1) << 3) + lr) * 128);
    u32 a_c0  = (u32)((qq >> 1) << 4);
    u32 b_row = (u32)((((qq >> 1) << 3) + lr) * 128);
    u32 b_c0  = (u32)((qq & 1) << 4);
    int cb = (lane & 3) * 2;

    for (int rb = wid; rb < 13; rb += 8) {
        float acc[25][4];
        #pragma unroll
        for (int t = 0; t < 25; t++)
            #pragma unroll
            for (int c = 0; c < 4; c++) acc[t][c] = 0.f;

        u32 abase = s_qh + (u32)(rb*2048) + a_row;
        #pragma unroll
        for (int ks = 0; ks < 4; ks++) {
            u32 acol = ((u32)(ks*32) + a_c0) ^ lsw;
            u32 ah[4], al[4];
            ldsm4(ah[0], ah[1], ah[2], ah[3], abase + acol);
            ldsm4(al[0], al[1], al[2], al[3], abase + 26624 + acol);
            u32 bcol = ((u32)(ks*32) + b_c0) ^ lsw;
            #pragma unroll
            for (int tp = 0; tp < 13; tp++) {
                u32 baddr = s_kh + (u32)(tp*2048) + b_row + bcol;
                u32 bh4[4], bl4[4];
                ldsm4(bh4[0], bh4[1], bh4[2], bh4[3], baddr);
                ldsm4(bl4[0], bl4[1], bl4[2], bl4[3], baddr + 26624);
                mma16816(acc[2*tp], ah, bh4[0], bh4[1]);
                mma16816(acc[2*tp], ah, bl4[0], bl4[1]);
                mma16816(acc[2*tp], al, bh4[0], bh4[1]);
                if (tp < 12) {
                    mma16816(acc[2*tp+1], ah, bh4[2], bh4[3]);
                    mma16816(acc[2*tp+1], ah, bl4[2], bl4[3]);
                    mma16816(acc[2*tp+1], al, bh4[2], bh4[3]);
                }
            }
        }

        float m0 = -1e30f, m1 = -1e30f;
        #pragma unroll
        for (int t = 0; t < 24; t++) {
            m0 = fmaxf(m0, fmaxf(acc[t][0], acc[t][1]));
            m1 = fmaxf(m1, fmaxf(acc[t][2], acc[t][3]));
        }
        {
            int c0 = 192 + cb;
            if (c0 < NN)     { m0 = fmaxf(m0, acc[24][0]); m1 = fmaxf(m1, acc[24][2]); }
            if (c0 + 1 < NN) { m0 = fmaxf(m0, acc[24][1]); m1 = fmaxf(m1, acc[24][3]); }
        }
        m0 = fmaxf(m0, __shfl_xor_sync(0xffffffffu, m0, 1));
        m0 = fmaxf(m0, __shfl_xor_sync(0xffffffffu, m0, 2));
        m1 = fmaxf(m1, __shfl_xor_sync(0xffffffffu, m1, 1));
        m1 = fmaxf(m1, __shfl_xor_sync(0xffffffffu, m1, 2));

        float s0 = 0.f, s1 = 0.f;
        float z00=0.f,z01=0.f,z02=0.f,z03=0.f;
        float z10=0.f,z11=0.f,z12=0.f,z13=0.f;
        #pragma unroll
        for (int t = 0; t < 25; t++) {
            int c0 = t*8 + cb;
            bool v0 = (t < 24) || (c0 < NN);
            bool v1 = (t < 24) || (c0 + 1 < NN);
            float e00 = v0 ? __expf(acc[t][0] - m0) : 0.f;
            float e01 = v1 ? __expf(acc[t][1] - m0) : 0.f;
            float e10 = v0 ? __expf(acc[t][2] - m1) : 0.f;
            float e11 = v1 ? __expf(acc[t][3] - m1) : 0.f;
            float4 va = *(const float4*)(vzs + c0*4);
            float4 vb = *(const float4*)(vzs + (c0+1)*4);
            s0 += e00 + e01; s1 += e10 + e11;
            z00 = fmaf(e00, va.x, fmaf(e01, vb.x, z00));
            z01 = fmaf(e00, va.y, fmaf(e01, vb.y, z01));
            z02 = fmaf(e00, va.z, fmaf(e01, vb.z, z02));
            z03 = fmaf(e00, va.w, fmaf(e01, vb.w, z03));
            z10 = fmaf(e10, va.x, fmaf(e11, vb.x, z10));
            z11 = fmaf(e10, va.y, fmaf(e11, vb.y, z11));
            z12 = fmaf(e10, va.z, fmaf(e11, vb.z, z12));
            z13 = fmaf(e10, va.w, fmaf(e11, vb.w, z13));
        }
        #pragma unroll
        for (int off = 1; off <= 2; off <<= 1) {
            s0  += __shfl_xor_sync(0xffffffffu, s0,  off);
            z00 += __shfl_xor_sync(0xffffffffu, z00, off);
            z01 += __shfl_xor_sync(0xffffffffu, z01, off);
            z02 += __shfl_xor_sync(0xffffffffu, z02, off);
            z03 += __shfl_xor_sync(0xffffffffu, z03, off);
            s1  += __shfl_xor_sync(0xffffffffu, s1,  off);
            z10 += __shfl_xor_sync(0xffffffffu, z10, off);
            z11 += __shfl_xor_sync(0xffffffffu, z11, off);
            z12 += __shfl_xor_sync(0xffffffffu, z12, off);
            z13 += __shfl_xor_sync(0xffffffffu, z13, off);
        }
        if ((lane & 3) == 0) {
            int r0 = rb*16 + (lane >> 2);
            if (r0 < NN) {
                float inv = 1.f / s0;
                *(float4*)(g_zpart + ((size_t)bh*NN + r0)*4) =
                    make_float4(z00*inv, z01*inv, z02*inv, z03*inv);
            }
            int r1 = r0 + 8;
            if (r1 < NN) {
                float inv = 1.f / s1;
                *(float4*)(g_zpart + ((size_t)bh*NN + r1)*4) =
                    make_float4(z10*inv, z11*inv, z12*inv, z13*inv);
            }
        }
    }
}

// ---------------- argmin + loss partial ----------------
__global__ void __launch_bounds__(256) argmin_kernel(const float* __restrict__ codebook,
                                                     const float* __restrict__ vq_in_b)
{
    __shared__ float4 cbs[DICN];
    __shared__ float  cns[DICN];
    __shared__ float  red[256];
    int tid = threadIdx.x;
    for (int c = tid; c < DICN; c += 256) {
        float4 e = *(const float4*)(codebook + c*4);
        cbs[c] = e;
        cns[c] = e.x*e.x + e.y*e.y + e.z*e.z + e.w*e.w;
    }
    __syncthreads();
    int p = blockIdx.x * 256 + tid;
    float lsum = 0.f;
    if (p < TOK) {
        int b = p / NN, n = p % NN;
        float z0 = vq_in_b[0], z1 = vq_in_b[1], z2 = vq_in_b[2], z3 = vq_in_b[3];
        #pragma unroll
        for (int h = 0; h < HH; h++) {
            float4 zp = *(const float4*)(g_zpart + (((size_t)b*HH + h)*NN + n)*4);
            z0 += zp.x; z1 += zp.y; z2 += zp.z; z3 += zp.w;
        }
        float best = 3.4e38f; int bi = 0;
        for (int c = 0; c < DICN; c++) {
            float4 e = cbs[c];
            float d = cns[c] - 2.f*(z0*e.x + z1*e.y + z2*e.z + z3*e.w);
            if (d < best) { best = d; bi = c; }
        }
        g_idx[p] = bi;
        float4 e = cbs[bi];
        float d0 = e.x - z0, d1 = e.y - z1, d2 = e.z - z2, d3 = e.w - z3;
        lsum = d0*d0 + d1*d1 + d2*d2 + d3*d3;
    }
    red[tid] = lsum;
    __syncthreads();
    for (int st = 128; st; st >>= 1) {
        if (tid < st) red[tid] += red[tid + st];
        __syncthreads();
    }
    if (tid == 0) g_losspart[blockIdx.x] = red[0];
}

// ---------------- gather ----------------
__global__ void gather_out(const float* __restrict__ codebook, float* __restrict__ out)
{
    int p = blockIdx.x;
    int ci = g_idx[p];
    float4 e = *(const float4*)(codebook + ci*4);
    for (int o = threadIdx.x; o < CC; o += 256) {
        float4 pr = *(const float4*)(g_P + o*4);
        out[(size_t)p*CC + o] =
            fmaf(e.x, pr.x, fmaf(e.y, pr.y, fmaf(e.z, pr.z, fmaf(e.w, pr.w, g_b2[o]))));
    }
}

__global__ void loss_final(float* __restrict__ dst)
{
    float s = 0.f;
    for (int i = threadIdx.x; i < 50; i += 32) s += g_losspart[i];
    #pragma unroll
    for (int off = 16; off; off >>= 1) s += __shfl_xor_sync(0xffffffffu, s, off);
    if (threadIdx.x == 0) dst[0] = 1.25f * s / 50432.0f;
}

// ---------------- launch ----------------
// Order matters for ncu: capture hits launch index 3 -> qk_mma.
extern "C" void kernel_launch(void* const* d_in, const int* in_sizes, int n_in,
                              void* d_out, int out_size)
{
    const float* x        = (const float*)d_in[0];
    const float* qkv_w    = (const float*)d_in[1];
    const float* proj_w   = (const float*)d_in[2];
    const float* proj_b   = (const float*)d_in[3];
    const float* vq_in_w  = (const float*)d_in[4];
    const float* vq_in_b  = (const float*)d_in[5];
    const float* vq_out_w = (const float*)d_in[6];
    const float* vq_out_b = (const float*)d_in[7];
    const float* codebook = (const float*)d_in[8];
    float* out = (float*)d_out;

    cudaFuncSetAttribute(attn_kernel, cudaFuncAttributeMaxDynamicSharedMemorySize, ATTN_SMEM);
    cudaFuncSetAttribute(qk_mma, cudaFuncAttributeMaxDynamicSharedMemorySize, 2*STAGE);

    __nv_bfloat16 *xh, *xl, *wh, *wl;
    cudaGetSymbolAddress((void**)&xh, g_xh);
    cudaGetSymbolAddress((void**)&xl, g_xl);
    cudaGetSymbolAddress((void**)&wh, g_wh);
    cudaGetSymbolAddress((void**)&wl, g_wl);

    conv_both<<<XBLK + WBLK, 256>>>(x, qkv_w, xh, xl, wh, wl);        // 0
    prep_m<<<48, 256>>>(qkv_w, vq_in_w);                              // 1
    prep_p<<<96, 256>>>(proj_w, proj_b, vq_out_w, vq_out_b);          // 2
    qk_mma<<<dim3(13, 197), 256, 2*STAGE>>>();                        // 3  <- ncu capture
    attn_kernel<<<BB*HH, 256, ATTN_SMEM>>>();                         // 4
    argmin_kernel<<<50, 256>>>(codebook, vq_in_b);                    // 5
    gather_out<<<TOK, 256>>>(codebook, out);                          // 6
    loss_final<<<1, 32>>>(out + (size_t)out_size - 1);                // 7
}

// round 14
// speedup vs baseline: 1.0525x; 1.0525x over previous
#include <cuda_runtime.h>
#include <cuda_bf16.h>
#include <math.h>

#define BB   64
#define NN   197
#define CC   768
#define HH   12
#define DD   64
#define DICN 1000
#define TOK  (BB*NN)           // 12608 = 64*197
#define QKC  1536              // q||k columns in g_qkh/g_qkl
#define WROWS 1664             // 1536 qk rows + 48 M rows + 80 pad = 13*128

typedef unsigned long long ull;
typedef unsigned int u32;

// ---- mma.sync / ldmatrix / cp.async helpers (baseline PTX, sm_80+) ----
__device__ __forceinline__ u32 smem_u32(const void* p) {
    u32 a; asm("{ .reg .u64 t; cvta.to.shared.u64 t, %1; cvt.u32.u64 %0, t; }" : "=r"(a) : "l"(p));
    return a;
}
__device__ __forceinline__ void ldsm4(u32& r0, u32& r1, u32& r2, u32& r3, u32 addr) {
    asm volatile("ldmatrix.sync.aligned.m8n8.x4.shared.b16 {%0,%1,%2,%3}, [%4];"
                 : "=r"(r0), "=r"(r1), "=r"(r2), "=r"(r3) : "r"(addr));
}
__device__ __forceinline__ void mma16816(float* d, const u32* a, u32 b0, u32 b1) {
    asm volatile("mma.sync.aligned.m16n8k16.row.col.f32.bf16.bf16.f32 "
                 "{%0,%1,%2,%3},{%4,%5,%6,%7},{%8,%9},{%0,%1,%2,%3};"
                 : "+f"(d[0]), "+f"(d[1]), "+f"(d[2]), "+f"(d[3])
                 : "r"(a[0]), "r"(a[1]), "r"(a[2]), "r"(a[3]), "r"(b0), "r"(b1));
}
__device__ __forceinline__ void cp16(u32 dst, const void* src) {
    asm volatile("cp.async.cg.shared.global [%0], [%1], 16;" :: "r"(dst), "l"(src) : "memory");
}
__device__ __forceinline__ void cp_commit() {
    asm volatile("cp.async.commit_group;" ::: "memory");
}

// split a float4 into bf16-hi (8B) and bf16-lo (8B)
__device__ __forceinline__ void split4(float4 v, uint2& hi, uint2& lo) {
    __nv_bfloat16 h0 = __float2bfloat16(v.x);
    __nv_bfloat16 h1 = __float2bfloat16(v.y);
    __nv_bfloat16 h2 = __float2bfloat16(v.z);
    __nv_bfloat16 h3 = __float2bfloat16(v.w);
    __nv_bfloat162 ph0(h0, h1), ph1(h2, h3);
    hi.x = *(u32*)&ph0; hi.y = *(u32*)&ph1;
    __nv_bfloat162 pl0(__float2bfloat16(v.x - __bfloat162float(h0)),
                       __float2bfloat16(v.y - __bfloat162float(h1)));
    __nv_bfloat162 pl1(__float2bfloat16(v.z - __bfloat162float(h2)),
                       __float2bfloat16(v.w - __bfloat162float(h3)));
    lo.x = *(u32*)&pl0; lo.y = *(u32*)&pl1;
}
// split a pair of floats into packed bf16x2 hi and lo
__device__ __forceinline__ void split2(float x, float y, u32& hi, u32& lo) {
    __nv_bfloat16 h0 = __float2bfloat16(x), h1 = __float2bfloat16(y);
    __nv_bfloat162 ph(h0, h1);
    hi = *(u32*)&ph;
    __nv_bfloat162 pl(__float2bfloat16(x - __bfloat162float(h0)),
                      __float2bfloat16(y - __bfloat162float(h1)));
    lo = *(u32*)&pl;
}

// ---------------- scratch ----------------
__device__ __nv_bfloat16 g_xh[TOK*CC];
__device__ __nv_bfloat16 g_xl[TOK*CC];
__device__ __nv_bfloat16 g_wh[WROWS*CC];
__device__ __nv_bfloat16 g_wl[WROWS*CC];
__device__ __nv_bfloat16 g_qkh[(size_t)TOK*QKC];  // bf16-hi of q(scaled)||k
__device__ __nv_bfloat16 g_qkl[(size_t)TOK*QKC];  // bf16-lo
__device__ float g_vz[BB*HH*NN*4];
__device__ float g_zpart[BB*HH*NN*4];
__device__ int   g_idx[TOK];
__device__ float g_P[CC*4];
__device__ float g_b2[CC];
__device__ float g_losspart[64];

// ---------------- fused bf16 hi/lo split conversion: x then qkv_w[0:1536] ----------------
#define XN4 (TOK*CC/4)
#define WN4 (1536*CC/4)
#define XBLK ((XN4 + 255) / 256)
#define WBLK ((WN4 + 255) / 256)

__global__ void conv_both(const float* __restrict__ x, const float* __restrict__ w,
                          __nv_bfloat16* __restrict__ xh, __nv_bfloat16* __restrict__ xl,
                          __nv_bfloat16* __restrict__ wh, __nv_bfloat16* __restrict__ wl)
{
    int blk = blockIdx.x;
    const float* src; __nv_bfloat16 *hi, *lo; int i, n4;
    if (blk < XBLK) {
        i = blk * 256 + threadIdx.x; n4 = XN4;
        src = x; hi = xh; lo = xl;
    } else {
        i = (blk - XBLK) * 256 + threadIdx.x; n4 = WN4;
        src = w; hi = wh; lo = wl;
    }
    if (i >= n4) return;
    float4 v = *(const float4*)(src + (size_t)i*4);
    uint2 h, l;
    split4(v, h, l);
    *(uint2*)(hi + (size_t)i*4) = h;
    *(uint2*)(lo + (size_t)i*4) = l;
}

// ---------------- prep: M row r=h*4+j of W (rows 1536..1583), bf16 hi/lo direct ----------------
__global__ void prep_m(const float* __restrict__ qkv_w, const float* __restrict__ vq_in_w)
{
    int h = blockIdx.x >> 2, j = blockIdx.x & 3;
    int r = 1536 + h*4 + j;
    for (int c = threadIdx.x; c < CC; c += blockDim.x) {
        float s = 0.f;
        #pragma unroll 8
        for (int d = 0; d < DD; d++)
            s = fmaf(qkv_w[(size_t)(2*CC + h*DD + d)*CC + c], vq_in_w[j*CC + h*DD + d], s);
        __nv_bfloat16 hb = __float2bfloat16(s);
        g_wh[(size_t)r*CC + c] = hb;
        g_wl[(size_t)r*CC + c] = __float2bfloat16(s - __bfloat162float(hb));
    }
}

__global__ void prep_p(const float* __restrict__ proj_w, const float* __restrict__ proj_b,
                       const float* __restrict__ vq_out_w, const float* __restrict__ vq_out_b)
{
    int wid = threadIdx.x >> 5, lane = threadIdx.x & 31;
    int o = blockIdx.x * 8 + wid;
    if (o >= CC) return;
    float p0=0.f,p1=0.f,p2=0.f,p3=0.f,bb=0.f;
    for (int c = lane; c < CC; c += 32) {
        float w = proj_w[(size_t)o*CC + c];
        float4 vo = *(const float4*)(vq_out_w + c*4);
        p0 = fmaf(w, vo.x, p0); p1 = fmaf(w, vo.y, p1);
        p2 = fmaf(w, vo.z, p2); p3 = fmaf(w, vo.w, p3);
        bb = fmaf(w, vq_out_b[c], bb);
    }
    #pragma unroll
    for (int off = 16; off; off >>= 1) {
        p0 += __shfl_xor_sync(0xffffffffu, p0, off);
        p1 += __shfl_xor_sync(0xffffffffu, p1, off);
        p2 += __shfl_xor_sync(0xffffffffu, p2, off);
        p3 += __shfl_xor_sync(0xffffffffu, p3, off);
        bb += __shfl_xor_sync(0xffffffffu, bb, off);
    }
    if (lane == 0) {
        *(float4*)(g_P + o*4) = make_float4(p0, p1, p2, p3);
        g_b2[o] = bb + proj_b[o];
    }
}

// ---------------- qk+vz GEMM on HMMA (round-12 proven config) ----------------
// CTA: 128 threads, 64(M) x 128(N) tile, 4 warps (1x4), warp tile 64x32.
// Stage 48KB, 2 stages = 96KB -> 2 CTAs/SM.
#define STAGE 49152

__global__ void __launch_bounds__(128, 2) qk_mma()
{
    extern __shared__ __align__(128) char smem[];
    u32 sbase = smem_u32(smem);
    int tid = threadIdx.x;
    int wid = tid >> 5, lane = tid & 31;
    int wn = wid;                       // 0..3
    int m0 = blockIdx.y * 64;           // 197 m-tiles, exact
    int c0 = blockIdx.x * 128;

    int q = lane >> 3, lr = lane & 7;
    u32 arow[4], asw[4];
    #pragma unroll
    for (int mf = 0; mf < 4; mf++) {
        int r = mf*16 + ((q & 1) << 3) + lr;          // 0..63
        arow[mf] = (u32)(r * 128);
        asw[mf]  = (u32)((r & 7) << 4);
    }
    u32 akb = (u32)((q >> 1) << 4);
    u32 brow[2], bsw[2];
    #pragma unroll
    for (int g = 0; g < 2; g++) {
        int nr = wn*32 + g*16 + ((q >> 1) << 3) + lr; // 0..127
        brow[g] = (u32)(nr * 128);
        bsw[g]  = (u32)((nr & 7) << 4);
    }
    u32 bkb = (u32)((q & 1) << 4);

    float acc[4][4][4];
    #pragma unroll
    for (int a = 0; a < 4; a++)
        #pragma unroll
        for (int b = 0; b < 4; b++)
            #pragma unroll
            for (int c = 0; c < 4; c++) acc[a][b][c] = 0.f;

    auto fill = [&](int buf, int t) {
        int k0 = t * 64;
        u32 db = sbase + buf*STAGE;
        #pragma unroll
        for (int i = 0; i < 4; i++) {
            int u = i*128 + tid;
            int row = u >> 3, ku = u & 7;
            u32 soff = (u32)(row*128 + ((ku*16) ^ ((row & 7) << 4)));
            size_t aoff = (size_t)(m0 + row)*CC + k0 + ku*8;
            cp16(db + soff,        g_xh + aoff);
            cp16(db + 8192 + soff, g_xl + aoff);
        }
        #pragma unroll
        for (int i = 0; i < 8; i++) {
            int u = i*128 + tid;
            int row = u >> 3, ku = u & 7;
            u32 soff = (u32)(row*128 + ((ku*16) ^ ((row & 7) << 4)));
            size_t boff = (size_t)(c0 + row)*CC + k0 + ku*8;
            cp16(db + 16384 + soff, g_wh + boff);
            cp16(db + 32768 + soff, g_wl + boff);
        }
        cp_commit();
    };

    fill(0, 0);
    for (int t = 0; t < 12; t++) {
        int buf = t & 1;
        if (t + 1 < 12) {
            fill(buf ^ 1, t + 1);
            asm volatile("cp.async.wait_group 1;" ::: "memory");
        } else {
            asm volatile("cp.async.wait_group 0;" ::: "memory");
        }
        __syncthreads();

        u32 Ab  = sbase + buf*STAGE;
        u32 Alb = Ab + 8192;
        u32 Bb  = Ab + 16384;
        u32 Blb = Ab + 32768;
        #pragma unroll
        for (int ks = 0; ks < 4; ks++) {
            u32 kb = (u32)(ks * 32);
            u32 Ah[4][4], Al[4][4], Bh[2][4], Bl[2][4];
            #pragma unroll
            for (int mf = 0; mf < 4; mf++) {
                u32 colA = (kb + akb) ^ asw[mf];
                ldsm4(Ah[mf][0], Ah[mf][1], Ah[mf][2], Ah[mf][3], Ab  + arow[mf] + colA);
                ldsm4(Al[mf][0], Al[mf][1], Al[mf][2], Al[mf][3], Alb + arow[mf] + colA);
            }
            #pragma unroll
            for (int g = 0; g < 2; g++) {
                u32 colB = (kb + bkb) ^ bsw[g];
                ldsm4(Bh[g][0], Bh[g][1], Bh[g][2], Bh[g][3], Bb  + brow[g] + colB);
                ldsm4(Bl[g][0], Bl[g][1], Bl[g][2], Bl[g][3], Blb + brow[g] + colB);
            }
            #pragma unroll
            for (int mf = 0; mf < 4; mf++) {
                #pragma unroll
                for (int g = 0; g < 2; g++) {
                    mma16816(acc[mf][2*g],   Ah[mf], Bh[g][0], Bh[g][1]);
                    mma16816(acc[mf][2*g+1], Ah[mf], Bh[g][2], Bh[g][3]);
                    mma16816(acc[mf][2*g],   Ah[mf], Bl[g][0], Bl[g][1]);
                    mma16816(acc[mf][2*g+1], Ah[mf], Bl[g][2], Bl[g][3]);
                    mma16816(acc[mf][2*g],   Al[mf], Bh[g][0], Bh[g][1]);
                    mma16816(acc[mf][2*g+1], Al[mf], Bh[g][2], Bh[g][3]);
                }
            }
        }
        __syncthreads();
    }

    int rb = m0 + (lane >> 2);
    int nb = c0 + wn*32 + (lane & 3)*2;
    if (c0 < 1536) {
        float scale = (c0 < 768) ? 0.125f : 1.0f;
        #pragma unroll
        for (int mf = 0; mf < 4; mf++) {
            #pragma unroll
            for (int nf = 0; nf < 4; nf++) {
                int r = rb + mf*16;
                int n = nb + nf*8;
                u32 hi, lo;
                split2(acc[mf][nf][0]*scale, acc[mf][nf][1]*scale, hi, lo);
                *(u32*)(g_qkh + (size_t)r*QKC + n) = hi;
                *(u32*)(g_qkl + (size_t)r*QKC + n) = lo;
                split2(acc[mf][nf][2]*scale, acc[mf][nf][3]*scale, hi, lo);
                *(u32*)(g_qkh + (size_t)(r+8)*QKC + n) = hi;
                *(u32*)(g_qkl + (size_t)(r+8)*QKC + n) = lo;
            }
        }
    } else {
        #pragma unroll
        for (int mf = 0; mf < 4; mf++) {
            #pragma unroll
            for (int nf = 0; nf < 4; nf++) {
                int col = nb + nf*8 - 1536;
                if (col >= 48) continue;
                #pragma unroll
                for (int rr = 0; rr < 2; rr++) {
                    int r = rb + mf*16 + rr*8;
                    int bb2 = r / NN, nn = r - bb2*NN;
                    float v0 = acc[mf][nf][rr*2], v1 = acc[mf][nf][rr*2 + 1];
                    g_vz[((size_t)(bb2*HH + (col >> 2))*NN + nn)*4 + (col & 3)] = v0;
                    if (col + 1 < 48)
                        g_vz[((size_t)(bb2*HH + ((col+1) >> 2))*NN + nn)*4 + ((col+1) & 3)] = v1;
                }
            }
        }
    }
}

// ---------------- fused attention on HMMA, split 2 CTAs per (b,h) ----------------
// CTA (bh, half): half 0 -> rb 0..6 (q rows 0..111), half 1 -> rb 7..12 (q rows 112..207).
// smem: qh[112][64]b16 @0 (14336), ql @14336, kh[208] @28672 (26624), kl @55296,
//       vz float[200][4] @81920 (3200) -> 85120 B -> 2 CTAs/SM.
#define ATTN_SMEM 85120

__global__ void __launch_bounds__(128, 2) attn_kernel()
{
    extern __shared__ __align__(128) char sm[];
    u32 s_qh = smem_u32(sm);
    u32 s_kh = s_qh + 28672;
    float* vzs = (float*)(sm + 81920);

    int bh = blockIdx.x;
    int half = blockIdx.y;
    int rb0 = half * 7;
    int nblk = half ? 6 : 7;
    int qrow0 = rb0 * 16;             // 0 or 112
    int nqrows = nblk * 16;           // 112 or 96
    int b = bh / HH, h = bh % HH;
    const __nv_bfloat16* qhp = g_qkh + (size_t)(b*NN)*QKC + h*64;
    const __nv_bfloat16* qlp = g_qkl + (size_t)(b*NN)*QKC + h*64;
    int tid = threadIdx.x;

    // q half (hi/lo) into swizzled smem; rows >= NN zero-padded
    for (int u = tid; u < nqrows*8; u += 128) {
        int row = u >> 3, ch = u & 7;
        int grow = qrow0 + row;
        u32 off = (u32)(row*128 + ((ch*16) ^ ((row & 7) << 4)));
        if (grow < NN) {
            size_t src = (size_t)grow*QKC + ch*8;
            cp16(s_qh + off,         qhp + src);
            cp16(s_qh + 14336 + off, qlp + src);
        } else {
            uint4 z = make_uint4(0u,0u,0u,0u);
            *(uint4*)(sm + off)         = z;
            *(uint4*)(sm + 14336 + off) = z;
        }
    }
    // k full (hi/lo)
    for (int u = tid; u < NN*8; u += 128) {
        int row = u >> 3, ch = u & 7;
        u32 off = (u32)(row*128 + ((ch*16) ^ ((row & 7) << 4)));
        size_t src = (size_t)row*QKC + ch*8;
        cp16(s_kh + off,         qhp + 768 + src);
        cp16(s_kh + 26624 + off, qlp + 768 + src);
    }
    cp_commit();
    // pad k rows 197..207
    for (int u = tid; u < 88; u += 128) {
        int row = 197 + (u >> 3), ch = u & 7;
        u32 off = (u32)(row*128 + ((ch*16) ^ ((row & 7) << 4)));
        uint4 z = make_uint4(0u,0u,0u,0u);
        *(uint4*)(sm + 28672 + off) = z;
        *(uint4*)(sm + 55296 + off) = z;
    }
    // vz, pad to 200
    {
        size_t vb = (size_t)bh*NN*4;
        for (int i = tid; i < 200*4; i += 128)
            vzs[i] = (i < NN*4) ? g_vz[vb + i] : 0.f;
    }
    asm volatile("cp.async.wait_group 0;" ::: "memory");
    __syncthreads();

    int lane = tid & 31, wid = tid >> 5;
    int qq = lane >> 3, lr = lane & 7;
    u32 lsw = (u32)(lr << 4);
    u32 a_row = (u32)((((qq & 1) << 3) + lr) * 128);
    u32 a_c0  = (u32)((qq >> 1) << 4);
    u32 b_row = (u32)((((qq >> 1) << 3) + lr) * 128);
    u32 b_c0  = (u32)((qq & 1) << 4);
    int cb = (lane & 3) * 2;

    for (int i = wid; i < nblk; i += 4) {
        int rb = rb0 + i;             // global row-block (output rows rb*16..)
        float acc[25][4];
        #pragma unroll
        for (int t = 0; t < 25; t++)
            #pragma unroll
            for (int c = 0; c < 4; c++) acc[t][c] = 0.f;

        u32 abase = s_qh + (u32)(i*2048) + a_row;    // local block index
        #pragma unroll
        for (int ks = 0; ks < 4; ks++) {
            u32 acol = ((u32)(ks*32) + a_c0) ^ lsw;
            u32 ah[4], al[4];
            ldsm4(ah[0], ah[1], ah[2], ah[3], abase + acol);
            ldsm4(al[0], al[1], al[2], al[3], abase + 14336 + acol);
            u32 bcol = ((u32)(ks*32) + b_c0) ^ lsw;
            #pragma unroll
            for (int tp = 0; tp < 13; tp++) {
                u32 baddr = s_kh + (u32)(tp*2048) + b_row + bcol;
                u32 bh4[4], bl4[4];
                ldsm4(bh4[0], bh4[1], bh4[2], bh4[3], baddr);
                ldsm4(bl4[0], bl4[1], bl4[2], bl4[3], baddr + 26624);
                mma16816(acc[2*tp], ah, bh4[0], bh4[1]);
                mma16816(acc[2*tp], ah, bl4[0], bl4[1]);
                mma16816(acc[2*tp], al, bh4[0], bh4[1]);
                if (tp < 12) {
                    mma16816(acc[2*tp+1], ah, bh4[2], bh4[3]);
                    mma16816(acc[2*tp+1], ah, bl4[2], bl4[3]);
                    mma16816(acc[2*tp+1], al, bh4[2], bh4[3]);
                }
            }
        }

        float m0 = -1e30f, m1 = -1e30f;
        #pragma unroll
        for (int t = 0; t < 24; t++) {
            m0 = fmaxf(m0, fmaxf(acc[t][0], acc[t][1]));
            m1 = fmaxf(m1, fmaxf(acc[t][2], acc[t][3]));
        }
        {
            int c0 = 192 + cb;
            if (c0 < NN)     { m0 = fmaxf(m0, acc[24][0]); m1 = fmaxf(m1, acc[24][2]); }
            if (c0 + 1 < NN) { m0 = fmaxf(m0, acc[24][1]); m1 = fmaxf(m1, acc[24][3]); }
        }
        m0 = fmaxf(m0, __shfl_xor_sync(0xffffffffu, m0, 1));
        m0 = fmaxf(m0, __shfl_xor_sync(0xffffffffu, m0, 2));
        m1 = fmaxf(m1, __shfl_xor_sync(0xffffffffu, m1, 1));
        m1 = fmaxf(m1, __shfl_xor_sync(0xffffffffu, m1, 2));

        float s0 = 0.f, s1 = 0.f;
        float z00=0.f,z01=0.f,z02=0.f,z03=0.f;
        float z10=0.f,z11=0.f,z12=0.f,z13=0.f;
        #pragma unroll
        for (int t = 0; t < 25; t++) {
            int c0 = t*8 + cb;
            bool v0 = (t < 24) || (c0 < NN);
            bool v1 = (t < 24) || (c0 + 1 < NN);
            float e00 = v0 ? __expf(acc[t][0] - m0) : 0.f;
            float e01 = v1 ? __expf(acc[t][1] - m0) : 0.f;
            float e10 = v0 ? __expf(acc[t][2] - m1) : 0.f;
            float e11 = v1 ? __expf(acc[t][3] - m1) : 0.f;
            float4 va = *(const float4*)(vzs + c0*4);
            float4 vb = *(const float4*)(vzs + (c0+1)*4);
            s0 += e00 + e01; s1 += e10 + e11;
            z00 = fmaf(e00, va.x, fmaf(e01, vb.x, z00));
            z01 = fmaf(e00, va.y, fmaf(e01, vb.y, z01));
            z02 = fmaf(e00, va.z, fmaf(e01, vb.z, z02));
            z03 = fmaf(e00, va.w, fmaf(e01, vb.w, z03));
            z10 = fmaf(e10, va.x, fmaf(e11, vb.x, z10));
            z11 = fmaf(e10, va.y, fmaf(e11, vb.y, z11));
            z12 = fmaf(e10, va.z, fmaf(e11, vb.z, z12));
            z13 = fmaf(e10, va.w, fmaf(e11, vb.w, z13));
        }
        #pragma unroll
        for (int off = 1; off <= 2; off <<= 1) {
            s0  += __shfl_xor_sync(0xffffffffu, s0,  off);
            z00 += __shfl_xor_sync(0xffffffffu, z00, off);
            z01 += __shfl_xor_sync(0xffffffffu, z01, off);
            z02 += __shfl_xor_sync(0xffffffffu, z02, off);
            z03 += __shfl_xor_sync(0xffffffffu, z03, off);
            s1  += __shfl_xor_sync(0xffffffffu, s1,  off);
            z10 += __shfl_xor_sync(0xffffffffu, z10, off);
            z11 += __shfl_xor_sync(0xffffffffu, z11, off);
            z12 += __shfl_xor_sync(0xffffffffu, z12, off);
            z13 += __shfl_xor_sync(0xffffffffu, z13, off);
        }
        if ((lane & 3) == 0) {
            int r0 = rb*16 + (lane >> 2);
            if (r0 < NN) {
                float inv = 1.f / s0;
                *(float4*)(g_zpart + ((size_t)bh*NN + r0)*4) =
                    make_float4(z00*inv, z01*inv, z02*inv, z03*inv);
            }
            int r1 = r0 + 8;
            if (r1 < NN) {
                float inv = 1.f / s1;
                *(float4*)(g_zpart + ((size_t)bh*NN + r1)*4) =
                    make_float4(z10*inv, z11*inv, z12*inv, z13*inv);
            }
        }
    }
}

// ---------------- argmin + loss partial ----------------
__global__ void __launch_bounds__(256) argmin_kernel(const float* __restrict__ codebook,
                                                     const float* __restrict__ vq_in_b)
{
    __shared__ float4 cbs[DICN];
    __shared__ float  cns[DICN];
    __shared__ float  red[256];
    int tid = threadIdx.x;
    for (int c = tid; c < DICN; c += 256) {
        float4 e = *(const float4*)(codebook + c*4);
        cbs[c] = e;
        cns[c] = e.x*e.x + e.y*e.y + e.z*e.z + e.w*e.w;
    }
    __syncthreads();
    int p = blockIdx.x * 256 + tid;
    float lsum = 0.f;
    if (p < TOK) {
        int b = p / NN, n = p % NN;
        float z0 = vq_in_b[0], z1 = vq_in_b[1], z2 = vq_in_b[2], z3 = vq_in_b[3];
        #pragma unroll
        for (int h = 0; h < HH; h++) {
            float4 zp = *(const float4*)(g_zpart + (((size_t)b*HH + h)*NN + n)*4);
            z0 += zp.x; z1 += zp.y; z2 += zp.z; z3 += zp.w;
        }
        float best = 3.4e38f; int bi = 0;
        for (int c = 0; c < DICN; c++) {
            float4 e = cbs[c];
            float d = cns[c] - 2.f*(z0*e.x + z1*e.y + z2*e.z + z3*e.w);
            if (d < best) { best = d; bi = c; }
        }
        g_idx[p] = bi;
        float4 e = cbs[bi];
        float d0 = e.x - z0, d1 = e.y - z1, d2 = e.z - z2, d3 = e.w - z3;
        lsum = d0*d0 + d1*d1 + d2*d2 + d3*d3;
    }
    red[tid] = lsum;
    __syncthreads();
    for (int st = 128; st; st >>= 1) {
        if (tid < st) red[tid] += red[tid + st];
        __syncthreads();
    }
    if (tid == 0) g_losspart[blockIdx.x] = red[0];
}

// ---------------- gather ----------------
__global__ void gather_out(const float* __restrict__ codebook, float* __restrict__ out)
{
    int p = blockIdx.x;
    int ci = g_idx[p];
    float4 e = *(const float4*)(codebook + ci*4);
    for (int o = threadIdx.x; o < CC; o += 256) {
        float4 pr = *(const float4*)(g_P + o*4);
        out[(size_t)p*CC + o] =
            fmaf(e.x, pr.x, fmaf(e.y, pr.y, fmaf(e.z, pr.z, fmaf(e.w, pr.w, g_b2[o]))));
    }
}

__global__ void loss_final(float* __restrict__ dst)
{
    float s = 0.f;
    for (int i = threadIdx.x; i < 50; i += 32) s += g_losspart[i];
    #pragma unroll
    for (int off = 16; off; off >>= 1) s += __shfl_xor_sync(0xffffffffu, s, off);
    if (threadIdx.x == 0) dst[0] = 1.25f * s / 50432.0f;
}

// ---------------- launch ----------------
// Order matters for ncu: capture hits launch index 3 -> qk_mma.
extern "C" void kernel_launch(void* const* d_in, const int* in_sizes, int n_in,
                              void* d_out, int out_size)
{
    const float* x        = (const float*)d_in[0];
    const float* qkv_w    = (const float*)d_in[1];
    const float* proj_w   = (const float*)d_in[2];
    const float* proj_b   = (const float*)d_in[3];
    const float* vq_in_w  = (const float*)d_in[4];
    const float* vq_in_b  = (const float*)d_in[5];
    const float* vq_out_w = (const float*)d_in[6];
    const float* vq_out_b = (const float*)d_in[7];
    const float* codebook = (const float*)d_in[8];
    float* out = (float*)d_out;

    cudaFuncSetAttribute(attn_kernel, cudaFuncAttributeMaxDynamicSharedMemorySize, ATTN_SMEM);
    cudaFuncSetAttribute(qk_mma, cudaFuncAttributeMaxDynamicSharedMemorySize, 2*STAGE);

    __nv_bfloat16 *xh, *xl, *wh, *wl;
    cudaGetSymbolAddress((void**)&xh, g_xh);
    cudaGetSymbolAddress((void**)&xl, g_xl);
    cudaGetSymbolAddress((void**)&wh, g_wh);
    cudaGetSymbolAddress((void**)&wl, g_wl);

    conv_both<<<XBLK + WBLK, 256>>>(x, qkv_w, xh, xl, wh, wl);        // 0
    prep_m<<<48, 256>>>(qkv_w, vq_in_w);                              // 1
    prep_p<<<96, 256>>>(proj_w, proj_b, vq_out_w, vq_out_b);          // 2
    qk_mma<<<dim3(13, 197), 128, 2*STAGE>>>();                        // 3  <- ncu capture
    attn_kernel<<<dim3(BB*HH, 2), 128, ATTN_SMEM>>>();                // 4
    argmin_kernel<<<50, 256>>>(codebook, vq_in_b);                    // 5
    gather_out<<<TOK, 256>>>(codebook, out);                          // 6
    loss_final<<<1, 32>>>(out + (size_t)out_size - 1);                // 7
}

// round 15
// speedup vs baseline: 1.1135x; 1.0580x over previous
#include <cuda_runtime.h>
#include <cuda_bf16.h>
#include <math.h>

#define BB   64
#define NN   197
#define CC   768
#define HH   12
#define DD   64
#define DICN 1000
#define TOK  (BB*NN)           // 12608 = 64*197
#define QKC  1536              // q||k columns in g_qkh/g_qkl
#define WROWS 1664             // 1536 qk rows + 48 M rows + 80 pad = 13*128

typedef unsigned long long ull;
typedef unsigned int u32;

// ---- mma.sync / ldmatrix / cp.async helpers (baseline PTX, sm_80+) ----
__device__ __forceinline__ u32 smem_u32(const void* p) {
    u32 a; asm("{ .reg .u64 t; cvta.to.shared.u64 t, %1; cvt.u32.u64 %0, t; }" : "=r"(a) : "l"(p));
    return a;
}
__device__ __forceinline__ void ldsm4(u32& r0, u32& r1, u32& r2, u32& r3, u32 addr) {
    asm volatile("ldmatrix.sync.aligned.m8n8.x4.shared.b16 {%0,%1,%2,%3}, [%4];"
                 : "=r"(r0), "=r"(r1), "=r"(r2), "=r"(r3) : "r"(addr));
}
__device__ __forceinline__ void mma16816(float* d, const u32* a, u32 b0, u32 b1) {
    asm volatile("mma.sync.aligned.m16n8k16.row.col.f32.bf16.bf16.f32 "
                 "{%0,%1,%2,%3},{%4,%5,%6,%7},{%8,%9},{%0,%1,%2,%3};"
                 : "+f"(d[0]), "+f"(d[1]), "+f"(d[2]), "+f"(d[3])
                 : "r"(a[0]), "r"(a[1]), "r"(a[2]), "r"(a[3]), "r"(b0), "r"(b1));
}
__device__ __forceinline__ void cp16(u32 dst, const void* src) {
    asm volatile("cp.async.cg.shared.global [%0], [%1], 16;" :: "r"(dst), "l"(src) : "memory");
}
__device__ __forceinline__ void cp_commit() {
    asm volatile("cp.async.commit_group;" ::: "memory");
}

// split a float4 into bf16-hi (8B) and bf16-lo (8B)
__device__ __forceinline__ void split4(float4 v, uint2& hi, uint2& lo) {
    __nv_bfloat16 h0 = __float2bfloat16(v.x);
    __nv_bfloat16 h1 = __float2bfloat16(v.y);
    __nv_bfloat16 h2 = __float2bfloat16(v.z);
    __nv_bfloat16 h3 = __float2bfloat16(v.w);
    __nv_bfloat162 ph0(h0, h1), ph1(h2, h3);
    hi.x = *(u32*)&ph0; hi.y = *(u32*)&ph1;
    __nv_bfloat162 pl0(__float2bfloat16(v.x - __bfloat162float(h0)),
                       __float2bfloat16(v.y - __bfloat162float(h1)));
    __nv_bfloat162 pl1(__float2bfloat16(v.z - __bfloat162float(h2)),
                       __float2bfloat16(v.w - __bfloat162float(h3)));
    lo.x = *(u32*)&pl0; lo.y = *(u32*)&pl1;
}
// split a pair of floats into packed bf16x2 hi and lo
__device__ __forceinline__ void split2(float x, float y, u32& hi, u32& lo) {
    __nv_bfloat16 h0 = __float2bfloat16(x), h1 = __float2bfloat16(y);
    __nv_bfloat162 ph(h0, h1);
    hi = *(u32*)&ph;
    __nv_bfloat162 pl(__float2bfloat16(x - __bfloat162float(h0)),
                      __float2bfloat16(y - __bfloat162float(h1)));
    lo = *(u32*)&pl;
}

// ---------------- scratch ----------------
__device__ __nv_bfloat16 g_xh[TOK*CC];
__device__ __nv_bfloat16 g_xl[TOK*CC];
__device__ __nv_bfloat16 g_wh[WROWS*CC];
__device__ __nv_bfloat16 g_wl[WROWS*CC];
__device__ __nv_bfloat16 g_qkh[(size_t)TOK*QKC];  // bf16-hi of q(scaled)||k
__device__ __nv_bfloat16 g_qkl[(size_t)TOK*QKC];  // bf16-lo
__device__ float g_vz[BB*HH*NN*4];
__device__ float g_zpart[BB*HH*NN*4];
__device__ int   g_idx[TOK];
__device__ float g_P[CC*4];
__device__ float g_b2[CC];
__device__ float g_cns[DICN];
__device__ float g_losspart[64];

// ---------------- codebook norms (launch 0; also pads ncu capture index) ----------------
__global__ void cbnorm(const float* __restrict__ codebook)
{
    int c = blockIdx.x * 256 + threadIdx.x;
    if (c >= DICN) return;
    float4 e = *(const float4*)(codebook + c*4);
    g_cns[c] = e.x*e.x + e.y*e.y + e.z*e.z + e.w*e.w;
}

// ---------------- fused setup: conv x | conv w | prep_m | prep_p ----------------
#define XN4 (TOK*CC/4)
#define WN4 (1536*CC/4)
#define XBLK (XN4 / 256)       // 9456, exact
#define WBLK (WN4 / 256)       // 1152, exact
#define SETUP_BLOCKS (XBLK + WBLK + 48 + 96)

__global__ void setup_fused(const float* __restrict__ x, const float* __restrict__ qkv_w,
                            const float* __restrict__ vq_in_w,
                            const float* __restrict__ proj_w, const float* __restrict__ proj_b,
                            const float* __restrict__ vq_out_w, const float* __restrict__ vq_out_b,
                            __nv_bfloat16* __restrict__ xh, __nv_bfloat16* __restrict__ xl,
                            __nv_bfloat16* __restrict__ wh, __nv_bfloat16* __restrict__ wl)
{
    int blk = blockIdx.x;
    int tid = threadIdx.x;
    if (blk < XBLK + WBLK) {
        // bf16 hi/lo split conversion
        const float* src; __nv_bfloat16 *hi, *lo; int i;
        if (blk < XBLK) { i = blk * 256 + tid; src = x; hi = xh; lo = xl; }
        else            { i = (blk - XBLK) * 256 + tid; src = qkv_w; hi = wh; lo = wl; }
        float4 v = *(const float4*)(src + (size_t)i*4);
        uint2 h, l;
        split4(v, h, l);
        *(uint2*)(hi + (size_t)i*4) = h;
        *(uint2*)(lo + (size_t)i*4) = l;
    } else if (blk < XBLK + WBLK + 48) {
        // prep_m: M row r=h*4+j of W (rows 1536..1583), bf16 hi/lo direct
        int pm = blk - (XBLK + WBLK);
        int h = pm >> 2, j = pm & 3;
        int r = 1536 + h*4 + j;
        for (int c = tid; c < CC; c += 256) {
            float s = 0.f;
            #pragma unroll 8
            for (int d = 0; d < DD; d++)
                s = fmaf(qkv_w[(size_t)(2*CC + h*DD + d)*CC + c], vq_in_w[j*CC + h*DD + d], s);
            __nv_bfloat16 hb = __float2bfloat16(s);
            g_wh[(size_t)r*CC + c] = hb;
            g_wl[(size_t)r*CC + c] = __float2bfloat16(s - __bfloat162float(hb));
        }
    } else {
        // prep_p
        int pp = blk - (XBLK + WBLK + 48);
        int wid = tid >> 5, lane = tid & 31;
        int o = pp * 8 + wid;
        if (o >= CC) return;
        float p0=0.f,p1=0.f,p2=0.f,p3=0.f,bb=0.f;
        for (int c = lane; c < CC; c += 32) {
            float w = proj_w[(size_t)o*CC + c];
            float4 vo = *(const float4*)(vq_out_w + c*4);
            p0 = fmaf(w, vo.x, p0); p1 = fmaf(w, vo.y, p1);
            p2 = fmaf(w, vo.z, p2); p3 = fmaf(w, vo.w, p3);
            bb = fmaf(w, vq_out_b[c], bb);
        }
        #pragma unroll
        for (int off = 16; off; off >>= 1) {
            p0 += __shfl_xor_sync(0xffffffffu, p0, off);
            p1 += __shfl_xor_sync(0xffffffffu, p1, off);
            p2 += __shfl_xor_sync(0xffffffffu, p2, off);
            p3 += __shfl_xor_sync(0xffffffffu, p3, off);
            bb += __shfl_xor_sync(0xffffffffu, bb, off);
        }
        if (lane == 0) {
            *(float4*)(g_P + o*4) = make_float4(p0, p1, p2, p3);
            g_b2[o] = bb + proj_b[o];
        }
    }
}

// ---------------- qk+vz GEMM on HMMA (round-12 proven config) ----------------
// CTA: 128 threads, 64(M) x 128(N) tile, 4 warps (1x4), warp tile 64x32.
// Stage 48KB, 2 stages = 96KB -> 2 CTAs/SM.
#define STAGE 49152

__global__ void __launch_bounds__(128, 2) qk_mma()
{
    extern __shared__ __align__(128) char smem[];
    u32 sbase = smem_u32(smem);
    int tid = threadIdx.x;
    int wid = tid >> 5, lane = tid & 31;
    int wn = wid;                       // 0..3
    int m0 = blockIdx.y * 64;           // 197 m-tiles, exact
    int c0 = blockIdx.x * 128;

    int q = lane >> 3, lr = lane & 7;
    u32 arow[4], asw[4];
    #pragma unroll
    for (int mf = 0; mf < 4; mf++) {
        int r = mf*16 + ((q & 1) << 3) + lr;          // 0..63
        arow[mf] = (u32)(r * 128);
        asw[mf]  = (u32)((r & 7) << 4);
    }
    u32 akb = (u32)((q >> 1) << 4);
    u32 brow[2], bsw[2];
    #pragma unroll
    for (int g = 0; g < 2; g++) {
        int nr = wn*32 + g*16 + ((q >> 1) << 3) + lr; // 0..127
        brow[g] = (u32)(nr * 128);
        bsw[g]  = (u32)((nr & 7) << 4);
    }
    u32 bkb = (u32)((q & 1) << 4);

    float acc[4][4][4];
    #pragma unroll
    for (int a = 0; a < 4; a++)
        #pragma unroll
        for (int b = 0; b < 4; b++)
            #pragma unroll
            for (int c = 0; c < 4; c++) acc[a][b][c] = 0.f;

    auto fill = [&](int buf, int t) {
        int k0 = t * 64;
        u32 db = sbase + buf*STAGE;
        #pragma unroll
        for (int i = 0; i < 4; i++) {
            int u = i*128 + tid;
            int row = u >> 3, ku = u & 7;
            u32 soff = (u32)(row*128 + ((ku*16) ^ ((row & 7) << 4)));
            size_t aoff = (size_t)(m0 + row)*CC + k0 + ku*8;
            cp16(db + soff,        g_xh + aoff);
            cp16(db + 8192 + soff, g_xl + aoff);
        }
        #pragma unroll
        for (int i = 0; i < 8; i++) {
            int u = i*128 + tid;
            int row = u >> 3, ku = u & 7;
            u32 soff = (u32)(row*128 + ((ku*16) ^ ((row & 7) << 4)));
            size_t boff = (size_t)(c0 + row)*CC + k0 + ku*8;
            cp16(db + 16384 + soff, g_wh + boff);
            cp16(db + 32768 + soff, g_wl + boff);
        }
        cp_commit();
    };

    fill(0, 0);
    for (int t = 0; t < 12; t++) {
        int buf = t & 1;
        if (t + 1 < 12) {
            fill(buf ^ 1, t + 1);
            asm volatile("cp.async.wait_group 1;" ::: "memory");
        } else {
            asm volatile("cp.async.wait_group 0;" ::: "memory");
        }
        __syncthreads();

        u32 Ab  = sbase + buf*STAGE;
        u32 Alb = Ab + 8192;
        u32 Bb  = Ab + 16384;
        u32 Blb = Ab + 32768;
        #pragma unroll
        for (int ks = 0; ks < 4; ks++) {
            u32 kb = (u32)(ks * 32);
            u32 Ah[4][4], Al[4][4], Bh[2][4], Bl[2][4];
            #pragma unroll
            for (int mf = 0; mf < 4; mf++) {
                u32 colA = (kb + akb) ^ asw[mf];
                ldsm4(Ah[mf][0], Ah[mf][1], Ah[mf][2], Ah[mf][3], Ab  + arow[mf] + colA);
                ldsm4(Al[mf][0], Al[mf][1], Al[mf][2], Al[mf][3], Alb + arow[mf] + colA);
            }
            #pragma unroll
            for (int g = 0; g < 2; g++) {
                u32 colB = (kb + bkb) ^ bsw[g];
                ldsm4(Bh[g][0], Bh[g][1], Bh[g][2], Bh[g][3], Bb  + brow[g] + colB);
                ldsm4(Bl[g][0], Bl[g][1], Bl[g][2], Bl[g][3], Blb + brow[g] + colB);
            }
            #pragma unroll
            for (int mf = 0; mf < 4; mf++) {
                #pragma unroll
                for (int g = 0; g < 2; g++) {
                    mma16816(acc[mf][2*g],   Ah[mf], Bh[g][0], Bh[g][1]);
                    mma16816(acc[mf][2*g+1], Ah[mf], Bh[g][2], Bh[g][3]);
                    mma16816(acc[mf][2*g],   Ah[mf], Bl[g][0], Bl[g][1]);
                    mma16816(acc[mf][2*g+1], Ah[mf], Bl[g][2], Bl[g][3]);
                    mma16816(acc[mf][2*g],   Al[mf], Bh[g][0], Bh[g][1]);
                    mma16816(acc[mf][2*g+1], Al[mf], Bh[g][2], Bh[g][3]);
                }
            }
        }
        __syncthreads();
    }

    int rb = m0 + (lane >> 2);
    int nb = c0 + wn*32 + (lane & 3)*2;
    if (c0 < 1536) {
        float scale = (c0 < 768) ? 0.125f : 1.0f;
        #pragma unroll
        for (int mf = 0; mf < 4; mf++) {
            #pragma unroll
            for (int nf = 0; nf < 4; nf++) {
                int r = rb + mf*16;
                int n = nb + nf*8;
                u32 hi, lo;
                split2(acc[mf][nf][0]*scale, acc[mf][nf][1]*scale, hi, lo);
                *(u32*)(g_qkh + (size_t)r*QKC + n) = hi;
                *(u32*)(g_qkl + (size_t)r*QKC + n) = lo;
                split2(acc[mf][nf][2]*scale, acc[mf][nf][3]*scale, hi, lo);
                *(u32*)(g_qkh + (size_t)(r+8)*QKC + n) = hi;
                *(u32*)(g_qkl + (size_t)(r+8)*QKC + n) = lo;
            }
        }
    } else {
        #pragma unroll
        for (int mf = 0; mf < 4; mf++) {
            #pragma unroll
            for (int nf = 0; nf < 4; nf++) {
                int col = nb + nf*8 - 1536;
                if (col >= 48) continue;
                #pragma unroll
                for (int rr = 0; rr < 2; rr++) {
                    int r = rb + mf*16 + rr*8;
                    int bb2 = r / NN, nn = r - bb2*NN;
                    float v0 = acc[mf][nf][rr*2], v1 = acc[mf][nf][rr*2 + 1];
                    g_vz[((size_t)(bb2*HH + (col >> 2))*NN + nn)*4 + (col & 3)] = v0;
                    if (col + 1 < 48)
                        g_vz[((size_t)(bb2*HH + ((col+1) >> 2))*NN + nn)*4 + ((col+1) & 3)] = v1;
                }
            }
        }
    }
}

// ---------------- fused attention on HMMA, split 2 CTAs per (b,h) ----------------
#define ATTN_SMEM 85120

__global__ void __launch_bounds__(128, 2) attn_kernel()
{
    extern __shared__ __align__(128) char sm[];
    u32 s_qh = smem_u32(sm);
    u32 s_kh = s_qh + 28672;
    float* vzs = (float*)(sm + 81920);

    int bh = blockIdx.x;
    int half = blockIdx.y;
    int rb0 = half * 7;
    int nblk = half ? 6 : 7;
    int qrow0 = rb0 * 16;
    int nqrows = nblk * 16;
    int b = bh / HH, h = bh % HH;
    const __nv_bfloat16* qhp = g_qkh + (size_t)(b*NN)*QKC + h*64;
    const __nv_bfloat16* qlp = g_qkl + (size_t)(b*NN)*QKC + h*64;
    int tid = threadIdx.x;

    for (int u = tid; u < nqrows*8; u += 128) {
        int row = u >> 3, ch = u & 7;
        int grow = qrow0 + row;
        u32 off = (u32)(row*128 + ((ch*16) ^ ((row & 7) << 4)));
        if (grow < NN) {
            size_t src = (size_t)grow*QKC + ch*8;
            cp16(s_qh + off,         qhp + src);
            cp16(s_qh + 14336 + off, qlp + src);
        } else {
            uint4 z = make_uint4(0u,0u,0u,0u);
            *(uint4*)(sm + off)         = z;
            *(uint4*)(sm + 14336 + off) = z;
        }
    }
    for (int u = tid; u < NN*8; u += 128) {
        int row = u >> 3, ch = u & 7;
        u32 off = (u32)(row*128 + ((ch*16) ^ ((row & 7) << 4)));
        size_t src = (size_t)row*QKC + ch*8;
        cp16(s_kh + off,         qhp + 768 + src);
        cp16(s_kh + 26624 + off, qlp + 768 + src);
    }
    cp_commit();
    for (int u = tid; u < 88; u += 128) {
        int row = 197 + (u >> 3), ch = u & 7;
        u32 off = (u32)(row*128 + ((ch*16) ^ ((row & 7) << 4)));
        uint4 z = make_uint4(0u,0u,0u,0u);
        *(uint4*)(sm + 28672 + off) = z;
        *(uint4*)(sm + 55296 + off) = z;
    }
    {
        size_t vb = (size_t)bh*NN*4;
        for (int i = tid; i < 200*4; i += 128)
            vzs[i] = (i < NN*4) ? g_vz[vb + i] : 0.f;
    }
    asm volatile("cp.async.wait_group 0;" ::: "memory");
    __syncthreads();

    int lane = tid & 31, wid = tid >> 5;
    int qq = lane >> 3, lr = lane & 7;
    u32 lsw = (u32)(lr << 4);
    u32 a_row = (u32)((((qq & 1) << 3) + lr) * 128);
    u32 a_c0  = (u32)((qq >> 1) << 4);
    u32 b_row = (u32)((((qq >> 1) << 3) + lr) * 128);
    u32 b_c0  = (u32)((qq & 1) << 4);
    int cb = (lane & 3) * 2;

    for (int i = wid; i < nblk; i += 4) {
        int rb = rb0 + i;
        float acc[25][4];
        #pragma unroll
        for (int t = 0; t < 25; t++)
            #pragma unroll
            for (int c = 0; c < 4; c++) acc[t][c] = 0.f;

        u32 abase = s_qh + (u32)(i*2048) + a_row;
        #pragma unroll
        for (int ks = 0; ks < 4; ks++) {
            u32 acol = ((u32)(ks*32) + a_c0) ^ lsw;
            u32 ah[4], al[4];
            ldsm4(ah[0], ah[1], ah[2], ah[3], abase + acol);
            ldsm4(al[0], al[1], al[2], al[3], abase + 14336 + acol);
            u32 bcol = ((u32)(ks*32) + b_c0) ^ lsw;
            #pragma unroll
            for (int tp = 0; tp < 13; tp++) {
                u32 baddr = s_kh + (u32)(tp*2048) + b_row + bcol;
                u32 bh4[4], bl4[4];
                ldsm4(bh4[0], bh4[1], bh4[2], bh4[3], baddr);
                ldsm4(bl4[0], bl4[1], bl4[2], bl4[3], baddr + 26624);
                mma16816(acc[2*tp], ah, bh4[0], bh4[1]);
                mma16816(acc[2*tp], ah, bl4[0], bl4[1]);
                mma16816(acc[2*tp], al, bh4[0], bh4[1]);
                if (tp < 12) {
                    mma16816(acc[2*tp+1], ah, bh4[2], bh4[3]);
                    mma16816(acc[2*tp+1], ah, bl4[2], bl4[3]);
                    mma16816(acc[2*tp+1], al, bh4[2], bh4[3]);
                }
            }
        }

        float m0 = -1e30f, m1 = -1e30f;
        #pragma unroll
        for (int t = 0; t < 24; t++) {
            m0 = fmaxf(m0, fmaxf(acc[t][0], acc[t][1]));
            m1 = fmaxf(m1, fmaxf(acc[t][2], acc[t][3]));
        }
        {
            int c0 = 192 + cb;
            if (c0 < NN)     { m0 = fmaxf(m0, acc[24][0]); m1 = fmaxf(m1, acc[24][2]); }
            if (c0 + 1 < NN) { m0 = fmaxf(m0, acc[24][1]); m1 = fmaxf(m1, acc[24][3]); }
        }
        m0 = fmaxf(m0, __shfl_xor_sync(0xffffffffu, m0, 1));
        m0 = fmaxf(m0, __shfl_xor_sync(0xffffffffu, m0, 2));
        m1 = fmaxf(m1, __shfl_xor_sync(0xffffffffu, m1, 1));
        m1 = fmaxf(m1, __shfl_xor_sync(0xffffffffu, m1, 2));

        float s0 = 0.f, s1 = 0.f;
        float z00=0.f,z01=0.f,z02=0.f,z03=0.f;
        float z10=0.f,z11=0.f,z12=0.f,z13=0.f;
        #pragma unroll
        for (int t = 0; t < 25; t++) {
            int c0 = t*8 + cb;
            bool v0 = (t < 24) || (c0 < NN);
            bool v1 = (t < 24) || (c0 + 1 < NN);
            float e00 = v0 ? __expf(acc[t][0] - m0) : 0.f;
            float e01 = v1 ? __expf(acc[t][1] - m0) : 0.f;
            float e10 = v0 ? __expf(acc[t][2] - m1) : 0.f;
            float e11 = v1 ? __expf(acc[t][3] - m1) : 0.f;
            float4 va = *(const float4*)(vzs + c0*4);
            float4 vb = *(const float4*)(vzs + (c0+1)*4);
            s0 += e00 + e01; s1 += e10 + e11;
            z00 = fmaf(e00, va.x, fmaf(e01, vb.x, z00));
            z01 = fmaf(e00, va.y, fmaf(e01, vb.y, z01));
            z02 = fmaf(e00, va.z, fmaf(e01, vb.z, z02));
            z03 = fmaf(e00, va.w, fmaf(e01, vb.w, z03));
            z10 = fmaf(e10, va.x, fmaf(e11, vb.x, z10));
            z11 = fmaf(e10, va.y, fmaf(e11, vb.y, z11));
            z12 = fmaf(e10, va.z, fmaf(e11, vb.z, z12));
            z13 = fmaf(e10, va.w, fmaf(e11, vb.w, z13));
        }
        #pragma unroll
        for (int off = 1; off <= 2; off <<= 1) {
            s0  += __shfl_xor_sync(0xffffffffu, s0,  off);
            z00 += __shfl_xor_sync(0xffffffffu, z00, off);
            z01 += __shfl_xor_sync(0xffffffffu, z01, off);
            z02 += __shfl_xor_sync(0xffffffffu, z02, off);
            z03 += __shfl_xor_sync(0xffffffffu, z03, off);
            s1  += __shfl_xor_sync(0xffffffffu, s1,  off);
            z10 += __shfl_xor_sync(0xffffffffu, z10, off);
            z11 += __shfl_xor_sync(0xffffffffu, z11, off);
            z12 += __shfl_xor_sync(0xffffffffu, z12, off);
            z13 += __shfl_xor_sync(0xffffffffu, z13, off);
        }
        if ((lane & 3) == 0) {
            int r0 = rb*16 + (lane >> 2);
            if (r0 < NN) {
                float inv = 1.f / s0;
                *(float4*)(g_zpart + ((size_t)bh*NN + r0)*4) =
                    make_float4(z00*inv, z01*inv, z02*inv, z03*inv);
            }
            int r1 = r0 + 8;
            if (r1 < NN) {
                float inv = 1.f / s1;
                *(float4*)(g_zpart + ((size_t)bh*NN + r1)*4) =
                    make_float4(z10*inv, z11*inv, z12*inv, z13*inv);
            }
        }
    }
}

// ---------------- argmin + loss partial ----------------
__global__ void __launch_bounds__(256) argmin_kernel(const float* __restrict__ codebook,
                                                     const float* __restrict__ vq_in_b)
{
    __shared__ float4 cbs[DICN];
    __shared__ float  cns[DICN];
    __shared__ float  red[256];
    int tid = threadIdx.x;
    for (int c = tid; c < DICN; c += 256) {
        cbs[c] = *(const float4*)(codebook + c*4);
        cns[c] = g_cns[c];
    }
    __syncthreads();
    int p = blockIdx.x * 256 + tid;
    float lsum = 0.f;
    if (p < TOK) {
        int b = p / NN, n = p % NN;
        float z0 = vq_in_b[0], z1 = vq_in_b[1], z2 = vq_in_b[2], z3 = vq_in_b[3];
        #pragma unroll
        for (int h = 0; h < HH; h++) {
            float4 zp = *(const float4*)(g_zpart + (((size_t)b*HH + h)*NN + n)*4);
            z0 += zp.x; z1 += zp.y; z2 += zp.z; z3 += zp.w;
        }
        float best = 3.4e38f; int bi = 0;
        for (int c = 0; c < DICN; c++) {
            float4 e = cbs[c];
            float d = cns[c] - 2.f*(z0*e.x + z1*e.y + z2*e.z + z3*e.w);
            if (d < best) { best = d; bi = c; }
        }
        g_idx[p] = bi;
        float4 e = cbs[bi];
        float d0 = e.x - z0, d1 = e.y - z1, d2 = e.z - z2, d3 = e.w - z3;
        lsum = d0*d0 + d1*d1 + d2*d2 + d3*d3;
    }
    red[tid] = lsum;
    __syncthreads();
    for (int st = 128; st; st >>= 1) {
        if (tid < st) red[tid] += red[tid + st];
        __syncthreads();
    }
    if (tid == 0) g_losspart[blockIdx.x] = red[0];
}

// ---------------- gather + fused loss (extra block) ----------------
__global__ void gather_out(const float* __restrict__ codebook, float* __restrict__ out,
                           float* __restrict__ loss_dst)
{
    int p = blockIdx.x;
    if (p == TOK) {
        if (threadIdx.x < 32) {
            float s = 0.f;
            for (int i = threadIdx.x; i < 50; i += 32) s += g_losspart[i];
            #pragma unroll
            for (int off = 16; off; off >>= 1) s += __shfl_xor_sync(0xffffffffu, s, off);
            if (threadIdx.x == 0) loss_dst[0] = 1.25f * s / 50432.0f;
        }
        return;
    }
    int ci = g_idx[p];
    float4 e = *(const float4*)(codebook + ci*4);
    for (int o = threadIdx.x; o < CC; o += 256) {
        float4 pr = *(const float4*)(g_P + o*4);
        out[(size_t)p*CC + o] =
            fmaf(e.x, pr.x, fmaf(e.y, pr.y, fmaf(e.z, pr.z, fmaf(e.w, pr.w, g_b2[o]))));
    }
}

// ---------------- launch ----------------
// Order matters for ncu: capture hits launch index 3 -> attn_kernel this round.
extern "C" void kernel_launch(void* const* d_in, const int* in_sizes, int n_in,
                              void* d_out, int out_size)
{
    const float* x        = (const float*)d_in[0];
    const float* qkv_w    = (const float*)d_in[1];
    const float* proj_w   = (const float*)d_in[2];
    const float* proj_b   = (const float*)d_in[3];
    const float* vq_in_w  = (const float*)d_in[4];
    const float* vq_in_b  = (const float*)d_in[5];
    const float* vq_out_w = (const float*)d_in[6];
    const float* vq_out_b = (const float*)d_in[7];
    const float* codebook = (const float*)d_in[8];
    float* out = (float*)d_out;

    cudaFuncSetAttribute(attn_kernel, cudaFuncAttributeMaxDynamicSharedMemorySize, ATTN_SMEM);
    cudaFuncSetAttribute(qk_mma, cudaFuncAttributeMaxDynamicSharedMemorySize, 2*STAGE);

    __nv_bfloat16 *xh, *xl, *wh, *wl;
    cudaGetSymbolAddress((void**)&xh, g_xh);
    cudaGetSymbolAddress((void**)&xl, g_xl);
    cudaGetSymbolAddress((void**)&wh, g_wh);
    cudaGetSymbolAddress((void**)&wl, g_wl);

    cbnorm<<<(DICN + 255)/256, 256>>>(codebook);                              // 0
    setup_fused<<<SETUP_BLOCKS, 256>>>(x, qkv_w, vq_in_w, proj_w, proj_b,
                                       vq_out_w, vq_out_b, xh, xl, wh, wl);   // 1
    qk_mma<<<dim3(13, 197), 128, 2*STAGE>>>();                                // 2
    attn_kernel<<<dim3(BB*HH, 2), 128, ATTN_SMEM>>>();                        // 3 <- ncu capture
    argmin_kernel<<<50, 256>>>(codebook, vq_in_b);                            // 4
    gather_out<<<TOK + 1, 256>>>(codebook, out, out + (size_t)out_size - 1);  // 5
}